// round 1
// baseline (speedup 1.0000x reference)
#include <cuda_runtime.h>
#include <cuda_bf16.h>
#include <math.h>

#define NUM_USERS 100000
#define NUM_ITEMS 50000
#define NROWS     150000      // NUM_USERS + NUM_ITEMS
#define NPAD      150016      // padded row count (multiple of 128)
#define EMB       64
#define NEDGES    2400000
#define NLAYERS   3
#define NEG_SLOPE 0.01f

#define SCAN_CHUNK 2048
#define NUM_CHUNKS ((NROWS + SCAN_CHUNK - 1) / SCAN_CHUNK)   // 74

// -------- persistent device scratch (no allocations allowed) --------
__device__ float g_ego [NPAD * EMB];
__device__ float g_side[NPAD * EMB];
__device__ int   g_row_ptr[NROWS + 1];
__device__ int   g_cursor [NROWS];       // doubles as histogram counts
__device__ int   g_col [NEDGES];
__device__ float g_val [NEDGES];
__device__ int   g_bsum[NUM_CHUNKS];
__device__ int   g_boff[NUM_CHUNKS];

// ---------------------------------------------------------------
// CSR build
// ---------------------------------------------------------------
__global__ void k_zero_counts() {
    int i = blockIdx.x * blockDim.x + threadIdx.x;
    if (i < NROWS) g_cursor[i] = 0;
}

__global__ void k_hist(const int* __restrict__ rows, int n_edges) {
    int e = blockIdx.x * blockDim.x + threadIdx.x;
    if (e < n_edges) atomicAdd(&g_cursor[rows[e]], 1);
}

__global__ void k_scan_sums() {
    int b = blockIdx.x, t = threadIdx.x;
    int base = b * SCAN_CHUNK + t * 8;
    int s = 0;
#pragma unroll
    for (int i = 0; i < 8; i++) {
        int idx = base + i;
        if (idx < NROWS) s += g_cursor[idx];
    }
    __shared__ int sh[256];
    sh[t] = s;
    __syncthreads();
    for (int d = 128; d > 0; d >>= 1) {
        if (t < d) sh[t] += sh[t + d];
        __syncthreads();
    }
    if (t == 0) g_bsum[b] = sh[0];
}

__global__ void k_scan_top() {
    if (threadIdx.x == 0) {
        int run = 0;
        for (int b = 0; b < NUM_CHUNKS; b++) {
            g_boff[b] = run;
            run += g_bsum[b];
        }
        g_row_ptr[NROWS] = run;
    }
}

__global__ void k_scan_final() {
    int b = blockIdx.x, t = threadIdx.x;
    int base = b * SCAN_CHUNK + t * 8;
    int v[8];
    int local = 0;
#pragma unroll
    for (int i = 0; i < 8; i++) {
        int idx = base + i;
        v[i] = (idx < NROWS) ? g_cursor[idx] : 0;
        local += v[i];
    }
    __shared__ int sh[256];
    sh[t] = local;
    __syncthreads();
    for (int d = 1; d < 256; d <<= 1) {
        int x = (t >= d) ? sh[t - d] : 0;
        __syncthreads();
        sh[t] += x;
        __syncthreads();
    }
    int exc = g_boff[b] + (t ? sh[t - 1] : 0);
#pragma unroll
    for (int i = 0; i < 8; i++) {
        int idx = base + i;
        if (idx < NROWS) g_row_ptr[idx] = exc;
        exc += v[i];
    }
}

__global__ void k_copy_cursor() {
    int i = blockIdx.x * blockDim.x + threadIdx.x;
    if (i < NROWS) g_cursor[i] = g_row_ptr[i];
}

__global__ void k_scatter(const int* __restrict__ rows,
                          const int* __restrict__ cols,
                          const float* __restrict__ vals, int n_edges) {
    int e = blockIdx.x * blockDim.x + threadIdx.x;
    if (e < n_edges) {
        int r = rows[e];
        int pos = atomicAdd(&g_cursor[r], 1);
        g_col[pos] = cols[e];
        g_val[pos] = vals[e];
    }
}

// ---------------------------------------------------------------
// init: ego = [user_emb; item_emb]; out[:, 0:64] = ego
// ---------------------------------------------------------------
__global__ void k_init(const float* __restrict__ user_emb,
                       const float* __restrict__ item_emb,
                       float* __restrict__ out) {
    int idx = blockIdx.x * blockDim.x + threadIdx.x;   // one float4 per thread
    if (idx >= NROWS * 16) return;
    int r = idx >> 4;
    int c4 = idx & 15;
    float4 v;
    if (r < NUM_USERS)
        v = ((const float4*)&user_emb[r * EMB])[c4];
    else
        v = ((const float4*)&item_emb[(r - NUM_USERS) * EMB])[c4];
    ((float4*)&g_ego[r * EMB])[c4] = v;
    ((float4*)&out[r * (EMB * (NLAYERS + 1))])[c4] = v;
}

// ---------------------------------------------------------------
// SpMM: side = A @ ego   (warp per row, CSR, no atomics)
// ---------------------------------------------------------------
__global__ void k_spmm() {
    int w = (blockIdx.x * blockDim.x + threadIdx.x) >> 5;
    int lane = threadIdx.x & 31;
    if (w >= NROWS) return;
    int s = g_row_ptr[w];
    int e = g_row_ptr[w + 1];
    float2 acc = make_float2(0.f, 0.f);
    for (int i = s; i < e; i++) {
        int c = __ldg(&g_col[i]);
        float v = __ldg(&g_val[i]);
        float2 x = *(const float2*)&g_ego[c * EMB + lane * 2];
        acc.x = fmaf(v, x.x, acc.x);
        acc.y = fmaf(v, x.y, acc.y);
    }
    *(float2*)&g_side[w * EMB + lane * 2] = acc;
}

// ---------------------------------------------------------------
// Transform: ego = lrelu(side@W1+b1) + lrelu((ego*side)@W2+b2)
//            out[:, (l+1)*64 : (l+2)*64] = ego / max(||ego||, eps)
// thread-per-row; W1/W2 broadcast from shared; side/u staged in shared
// ---------------------------------------------------------------
__device__ __forceinline__ float lrelu2(float a, float b) {
    float x = (a > 0.f) ? a : NEG_SLOPE * a;
    float y = (b > 0.f) ? b : NEG_SLOPE * b;
    return x + y;
}

__global__ void __launch_bounds__(128)
k_transform(const float* __restrict__ W1g, const float* __restrict__ b1g,
            const float* __restrict__ W2g, const float* __restrict__ b2g,
            float* __restrict__ out, int layer) {
    extern __shared__ float sh[];
    float* W1s   = sh;                 // 4096
    float* W2s   = sh + 4096;          // 4096
    float* b1s   = sh + 8192;          // 64
    float* b2s   = sh + 8256;          // 64
    float* sideS = sh + 8320;          // 128*65 = 8320
    float* uS    = sideS + 128 * 65;   // 8320

    int t = threadIdx.x;
    int base = blockIdx.x * 128;

    // load weights (coalesced float4)
#pragma unroll 4
    for (int i = t; i < 1024; i += 128) {
        ((float4*)W1s)[i] = ((const float4*)W1g)[i];
        ((float4*)W2s)[i] = ((const float4*)W2g)[i];
    }
    if (t < 64) { b1s[t] = b1g[t]; b2s[t] = b2g[t]; }

    // stage side + u = ego*side for the block's 128 rows (padded stride 65)
    const float4* sg = (const float4*)&g_side[(size_t)base * EMB];
    const float4* eg = (const float4*)&g_ego [(size_t)base * EMB];
#pragma unroll 4
    for (int i = t; i < 2048; i += 128) {
        float4 sv = sg[i];
        float4 ev = eg[i];
        int row = i >> 4;
        int c = (i & 15) * 4;
        float* ds = &sideS[row * 65 + c];
        float* du = &uS   [row * 65 + c];
        ds[0] = sv.x; ds[1] = sv.y; ds[2] = sv.z; ds[3] = sv.w;
        du[0] = ev.x * sv.x; du[1] = ev.y * sv.y;
        du[2] = ev.z * sv.z; du[3] = ev.w * sv.w;
    }
    __syncthreads();

    int r = base + t;
    if (r >= NROWS) return;

    const float* srow = &sideS[t * 65];
    const float* urow = &uS[t * 65];
    float* egor = &g_ego[(size_t)r * EMB];

    float sumsq = 0.f;
#pragma unroll
    for (int q = 0; q < 4; q++) {
        float acc1[16], acc2[16];
#pragma unroll
        for (int i = 0; i < 16; i++) {
            acc1[i] = b1s[q * 16 + i];
            acc2[i] = b2s[q * 16 + i];
        }
#pragma unroll 4
        for (int k = 0; k < 64; k++) {
            float s = srow[k];
            float u = urow[k];
            const float4* w1 = (const float4*)&W1s[k * 64 + q * 16];
            const float4* w2 = (const float4*)&W2s[k * 64 + q * 16];
#pragma unroll
            for (int i4 = 0; i4 < 4; i4++) {
                float4 a = w1[i4];
                float4 b = w2[i4];
                acc1[i4 * 4 + 0] = fmaf(s, a.x, acc1[i4 * 4 + 0]);
                acc1[i4 * 4 + 1] = fmaf(s, a.y, acc1[i4 * 4 + 1]);
                acc1[i4 * 4 + 2] = fmaf(s, a.z, acc1[i4 * 4 + 2]);
                acc1[i4 * 4 + 3] = fmaf(s, a.w, acc1[i4 * 4 + 3]);
                acc2[i4 * 4 + 0] = fmaf(u, b.x, acc2[i4 * 4 + 0]);
                acc2[i4 * 4 + 1] = fmaf(u, b.y, acc2[i4 * 4 + 1]);
                acc2[i4 * 4 + 2] = fmaf(u, b.z, acc2[i4 * 4 + 2]);
                acc2[i4 * 4 + 3] = fmaf(u, b.w, acc2[i4 * 4 + 3]);
            }
        }
#pragma unroll
        for (int i4 = 0; i4 < 4; i4++) {
            float4 o;
            o.x = lrelu2(acc1[i4 * 4 + 0], acc2[i4 * 4 + 0]);
            o.y = lrelu2(acc1[i4 * 4 + 1], acc2[i4 * 4 + 1]);
            o.z = lrelu2(acc1[i4 * 4 + 2], acc2[i4 * 4 + 2]);
            o.w = lrelu2(acc1[i4 * 4 + 3], acc2[i4 * 4 + 3]);
            sumsq += o.x * o.x + o.y * o.y + o.z * o.z + o.w * o.w;
            ((float4*)egor)[q * 4 + i4] = o;
        }
    }

    float inv = 1.0f / fmaxf(sqrtf(sumsq), 1e-12f);
    float4* orow = (float4*)&out[(size_t)r * (EMB * (NLAYERS + 1)) + (layer + 1) * EMB];
#pragma unroll
    for (int j4 = 0; j4 < 16; j4++) {
        float4 v = ((const float4*)egor)[j4];
        v.x *= inv; v.y *= inv; v.z *= inv; v.w *= inv;
        orow[j4] = v;
    }
}

// ---------------------------------------------------------------
extern "C" void kernel_launch(void* const* d_in, const int* in_sizes, int n_in,
                              void* d_out, int out_size) {
    const int*   adj_rows = (const int*)  d_in[0];
    const int*   adj_cols = (const int*)  d_in[1];
    const float* adj_vals = (const float*)d_in[2];
    const float* user_emb = (const float*)d_in[3];
    const float* item_emb = (const float*)d_in[4];
    const float* gc_w     = (const float*)d_in[5];
    const float* gc_b     = (const float*)d_in[6];
    const float* bi_w     = (const float*)d_in[7];
    const float* bi_b     = (const float*)d_in[8];
    float*       out      = (float*)d_out;

    int n_edges = in_sizes[0];

    const int smem_bytes = (4096 * 2 + 64 * 2 + 128 * 65 * 2) * (int)sizeof(float); // 99840
    static bool attr_set = false;
    // cudaFuncSetAttribute is idempotent and not a stream op; safe every call.
    cudaFuncSetAttribute(k_transform, cudaFuncAttributeMaxDynamicSharedMemorySize, smem_bytes);
    (void)attr_set;

    // ---- CSR build ----
    k_zero_counts<<<(NROWS + 255) / 256, 256>>>();
    k_hist<<<(n_edges + 255) / 256, 256>>>(adj_rows, n_edges);
    k_scan_sums<<<NUM_CHUNKS, 256>>>();
    k_scan_top<<<1, 32>>>();
    k_scan_final<<<NUM_CHUNKS, 256>>>();
    k_copy_cursor<<<(NROWS + 255) / 256, 256>>>();
    k_scatter<<<(n_edges + 255) / 256, 256>>>(adj_rows, adj_cols, adj_vals, n_edges);

    // ---- init ego + layer-0 output ----
    k_init<<<(NROWS * 16 + 255) / 256, 256>>>(user_emb, item_emb, out);

    // ---- layers ----
    int spmm_blocks = (NROWS * 32 + 255) / 256;        // warp per row
    int tr_blocks   = (NROWS + 127) / 128;
    for (int l = 0; l < NLAYERS; l++) {
        k_spmm<<<spmm_blocks, 256>>>();
        k_transform<<<tr_blocks, 128, smem_bytes>>>(
            gc_w + l * 4096, gc_b + l * 64,
            bi_w + l * 4096, bi_b + l * 64,
            out, l);
    }
}